// round 16
// baseline (speedup 1.0000x reference)
#include <cuda_runtime.h>
#include <cstdint>

// ---------------------------------------------------------------------------
// WindowAttention3D: B=768, N=144, C=512, H=16, hd=32, NW=96
// Round 16: GEMM fragment feeds via ldmatrix.x4 (16 LDSM vs 64 LDS per k-tile
//           per warp). Attention unchanged (R14). Pre-rounded tf32 operands.
// ---------------------------------------------------------------------------

#define B_TOT   768
#define NTOK    144
#define DIMC    512
#define NH      16
#define HD      32
#define NWIN    96
#define SCALE   0.17677669529663687f   // 1/sqrt(32)
#define NTOK2   (NTOK*NTOK)            // 20736
#define BHSTRIDE (NTOK*HD)             // 4608
#define MTOT    (B_TOT*NTOK)           // 110592

// Scratch (device globals; allocation-free rule)
__device__ float g_qkv[3u*768u*16u*144u*32u];   // [3][B][H][N][hd] (tf32 bits)
__device__ float g_ctx[768u*144u*512u];         // [B][N][C]        (tf32 bits)
__device__ float g_bias[16u*144u*144u];         // [H][N][N]        (fp32)
__device__ float g_xtf[110592u*512u];           // x as tf32 bits
__device__ float g_wqtf[1536u*512u];            // qkv_w as tf32 bits
__device__ float g_wptf[512u*512u];             // proj_w as tf32 bits

// ---------------------------------------------------------------------------
__device__ __forceinline__ uint32_t f2tf(float x) {
    uint32_t r;
    asm("cvt.rna.tf32.f32 %0, %1;" : "=r"(r) : "f"(x));
    return r;
}

__device__ __forceinline__ uint4 f2tf4(float4 v) {
    uint4 u;
    u.x = f2tf(v.x); u.y = f2tf(v.y); u.z = f2tf(v.z); u.w = f2tf(v.w);
    return u;
}

__device__ __forceinline__ void mma_tf32(float* c, const uint32_t* a, const uint32_t* b) {
    asm volatile(
        "mma.sync.aligned.m16n8k8.row.col.f32.tf32.tf32.f32 "
        "{%0,%1,%2,%3},{%4,%5,%6,%7},{%8,%9},{%0,%1,%2,%3};\n"
        : "+f"(c[0]), "+f"(c[1]), "+f"(c[2]), "+f"(c[3])
        : "r"(a[0]), "r"(a[1]), "r"(a[2]), "r"(a[3]), "r"(b[0]), "r"(b[1]));
}

__device__ __forceinline__ uint32_t smem_u32(const void* p) {
    uint32_t a;
    asm("{ .reg .u64 t; cvta.to.shared.u64 t, %1; cvt.u32.u64 %0, t; }" : "=r"(a) : "l"(p));
    return a;
}

__device__ __forceinline__ void ldsm4(uint32_t* r, uint32_t addr) {
    asm volatile("ldmatrix.sync.aligned.m8n8.x4.shared.b16 {%0,%1,%2,%3}, [%4];"
        : "=r"(r[0]), "=r"(r[1]), "=r"(r[2]), "=r"(r[3]) : "r"(addr));
}

__device__ __forceinline__ void cp16(uint32_t saddr, const void* g) {
    asm volatile("cp.async.cg.shared.global [%0], [%1], 16;" :: "r"(saddr), "l"(g));
}
#define CP_COMMIT() asm volatile("cp.async.commit_group;" ::: "memory")
#define CP_WAIT2()  asm volatile("cp.async.wait_group 2;"  ::: "memory")

// ---------------------------------------------------------------------------
// Kernel 0: expand relative position bias table -> g_bias[h][n][m]
// ---------------------------------------------------------------------------
__global__ __launch_bounds__(256) void bias_expand_kernel(
    const float* __restrict__ table, const int* __restrict__ rel)
{
    int i = blockIdx.x * 256 + threadIdx.x;
    const int total = NH * NTOK2;
    if (i >= total) return;
    int h  = i / NTOK2;
    int nm = i - h * NTOK2;
    g_bias[i] = table[rel[nm] * NH + h];
}

// ---------------------------------------------------------------------------
// Kernel 0b: fp32 -> tf32-rounded bits (float4 granular)
// ---------------------------------------------------------------------------
__global__ __launch_bounds__(256) void cvt_tf32_kernel(
    const float* __restrict__ in, float* __restrict__ out, int n4)
{
    int i = blockIdx.x * 256 + threadIdx.x;
    if (i >= n4) return;
    float4 v = ((const float4*)in)[i];
    ((uint4*)out)[i] = f2tf4(v);
}

// ---------------------------------------------------------------------------
// TF32 GEMM: Out[m,n] = sum_k A[m,k]*W[n,k] + bias[n]
// BM=256, BN=128, BK=16, 256 threads (8 warps, 4x2), warp tile 64x64.
// 4-stage cp.async pipeline; fragments fed by ldmatrix.x4.
// ---------------------------------------------------------------------------
#define BM 256
#define BN 128
#define BK 16
#define AST 20
#define AW (BM*AST)
#define BW (BN*AST)
#define STAGES 4
#define KTILES (DIMC/BK)
#define GEMM_SMEM (STAGES*(AW+BW)*4)

template <int MODE>
__global__ __launch_bounds__(256) void gemm_tc_kernel(
    const float* __restrict__ bias, float* __restrict__ Out)
{
    extern __shared__ uint32_t sh[];
    const uint32_t sbase = smem_u32(sh);

    const int nT = (MODE == 0) ? 12 : 4;
    const int m_tile = blockIdx.x / nT;
    const int n_tile = blockIdx.x - m_tile * nT;
    const int m0 = m_tile * BM, n0 = n_tile * BN;

    const int tid  = threadIdx.x;
    const int warp = tid >> 5, lane = tid & 31;
    const int wm = warp >> 1;
    const int wn = warp & 1;
    const int gm = lane >> 2, gk = lane & 3;

    const float* __restrict__ Aptr = (MODE == 0 ? g_xtf : g_ctx) + (size_t)m0 * DIMC;
    const float* __restrict__ Wptr = (MODE == 0 ? g_wqtf : g_wptf) + (size_t)n0 * DIMC;

    const int lr = tid >> 2;
    const int lc = (tid & 3) * 4;
    const uint32_t a_sm0 = sbase;
    const uint32_t b_sm0 = sbase + STAGES * AW * 4;

    // ldmatrix lane addressing: matrix mi = lane/8; row+=8 if mi odd; word+=4 if mi>=2
    const int lrow = (lane & 7) + ((lane >> 3) & 1) * 8;
    const int lwrd = (lane >> 4) * 4;
    const uint32_t a_lane = ((uint32_t)(wm * 64 + lrow) * AST + lwrd) * 4;
    const uint32_t b_lane = ((uint32_t)(wn * 64 + lrow) * AST + lwrd) * 4;

    float acc[4][8][4];
    #pragma unroll
    for (int im = 0; im < 4; im++)
        #pragma unroll
        for (int in = 0; in < 8; in++)
            #pragma unroll
            for (int l = 0; l < 4; l++) acc[im][in][l] = 0.f;

    auto issue = [&](int t) {
        const int st = t & (STAGES - 1);
        const int kf = t * BK;
        const uint32_t ab = a_sm0 + st * AW * 4;
        #pragma unroll
        for (int j = 0; j < 4; j++) {
            int r = lr + j * 64;
            cp16(ab + (r * AST + lc) * 4, Aptr + (size_t)r * DIMC + kf + lc);
        }
        const uint32_t bb = b_sm0 + st * BW * 4;
        #pragma unroll
        for (int j = 0; j < 2; j++) {
            int r = lr + j * 64;
            cp16(bb + (r * AST + lc) * 4, Wptr + (size_t)r * DIMC + kf + lc);
        }
    };

    issue(0); CP_COMMIT();
    issue(1); CP_COMMIT();
    issue(2); CP_COMMIT();

    for (int t = 0; t < KTILES; t++) {
        CP_WAIT2();
        __syncthreads();
        if (t + 3 < KTILES) issue(t + 3);
        CP_COMMIT();

        const int st = t & (STAGES - 1);
        const uint32_t a_st = a_sm0 + st * AW * 4;
        const uint32_t b_st = b_sm0 + st * BW * 4;

        #pragma unroll
        for (int kk = 0; kk < BK; kk += 8) {
            uint32_t afr[4][4], bfr[8][2];
            #pragma unroll
            for (int im = 0; im < 4; im++)
                ldsm4(afr[im], a_st + a_lane + (uint32_t)(im * 16 * AST + kk) * 4);
            #pragma unroll
            for (int j = 0; j < 4; j++) {
                uint32_t r[4];
                ldsm4(r, b_st + b_lane + (uint32_t)(j * 16 * AST + kk) * 4);
                bfr[2 * j    ][0] = r[0];
                bfr[2 * j + 1][0] = r[1];
                bfr[2 * j    ][1] = r[2];
                bfr[2 * j + 1][1] = r[3];
            }
            #pragma unroll
            for (int im = 0; im < 4; im++)
                #pragma unroll
                for (int in = 0; in < 8; in++)
                    mma_tf32(acc[im][in], afr[im], bfr[in]);
        }
    }

    #pragma unroll
    for (int im = 0; im < 4; im++) {
        #pragma unroll
        for (int half = 0; half < 2; half++) {
            int rg = m0 + wm * 64 + im * 16 + gm + half * 8;
            int b_idx = rg / NTOK;
            int ntk   = rg - b_idx * NTOK;
            #pragma unroll
            for (int in = 0; in < 8; in++) {
                int cg = n0 + wn * 64 + in * 8 + gk * 2;
                float v0 = acc[im][in][half * 2 + 0] + bias[cg];
                float v1 = acc[im][in][half * 2 + 1] + bias[cg + 1];
                if (MODE == 0) {
                    int which = cg >> 9;
                    int rem   = cg & 511;
                    int h     = rem >> 5;
                    int d     = rem & 31;
                    size_t dst = ((size_t)(which * B_TOT + b_idx) * NH + h) * BHSTRIDE
                               + (size_t)ntk * HD + d;
                    *(float2*)&g_qkv[dst] =
                        make_float2(__uint_as_float(f2tf(v0)), __uint_as_float(f2tf(v1)));
                } else {
                    *(float2*)&Out[(size_t)rg * DIMC + cg] = make_float2(v0, v1);
                }
            }
        }
    }
}

// ---------------------------------------------------------------------------
// Kernel 2: flash-style attention per (b,h). 288 threads (9 warps), 16 rows
// per warp; scores in registers; quad-shfl softmax; shfl C->A repack with
// normalization folded in. 2 CTAs/SM. (unchanged from R14)
// ---------------------------------------------------------------------------
#define AQ_ST 36
#define ATTN_SMEM (3 * NTOK * AQ_ST * 4)   // 62208 B

__global__ __launch_bounds__(288, 2) void attn_kernel(const float* __restrict__ mask)
{
    extern __shared__ uint32_t sm[];
    uint32_t* sq = sm;
    uint32_t* sk = sq + NTOK * AQ_ST;
    uint32_t* sv = sk + NTOK * AQ_ST;

    const int bh = blockIdx.x;
    const int b  = bh >> 4, h = bh & 15;
    const int w  = b % NWIN;

    const int tid  = threadIdx.x;
    const int warp = tid >> 5, lane = tid & 31;
    const int gm = lane >> 2, gk = lane & 3;
    const int rb = warp * 16;

    const size_t qbase = ((size_t)(0 * B_TOT + b) * NH + h) * BHSTRIDE;
    const size_t kbase = ((size_t)(1 * B_TOT + b) * NH + h) * BHSTRIDE;
    const size_t vbase = ((size_t)(2 * B_TOT + b) * NH + h) * BHSTRIDE;

    for (int i = tid; i < (NTOK * HD / 4); i += 288) {
        int row = i >> 3;
        int d   = (i & 7) << 2;
        *(uint4*)&sq[row * AQ_ST + d] = *(const uint4*)&g_qkv[qbase + (size_t)row * HD + d];
        *(uint4*)&sk[row * AQ_ST + d] = *(const uint4*)&g_qkv[kbase + (size_t)row * HD + d];
        *(uint4*)&sv[row * AQ_ST + d] = *(const uint4*)&g_qkv[vbase + (size_t)row * HD + d];
    }
    __syncthreads();

    const float* __restrict__ biasp = g_bias + (size_t)h * NTOK2;
    const float* __restrict__ maskp = mask   + (size_t)w * NTOK2;

    uint32_t qf[4][4];
    #pragma unroll
    for (int k8 = 0; k8 < 4; k8++) {
        qf[k8][0] = sq[(rb + gm    ) * AQ_ST + k8 * 8 + gk    ];
        qf[k8][1] = sq[(rb + gm + 8) * AQ_ST + k8 * 8 + gk    ];
        qf[k8][2] = sq[(rb + gm    ) * AQ_ST + k8 * 8 + gk + 4];
        qf[k8][3] = sq[(rb + gm + 8) * AQ_ST + k8 * 8 + gk + 4];
    }

    float p[18][4];
    #pragma unroll
    for (int ni = 0; ni < 18; ni++) {
        float acc[4] = {0.f, 0.f, 0.f, 0.f};
        #pragma unroll
        for (int k8 = 0; k8 < 4; k8++) {
            uint32_t bb[2] = {sk[(ni * 8 + gm) * AQ_ST + k8 * 8 + gk],
                              sk[(ni * 8 + gm) * AQ_ST + k8 * 8 + gk + 4]};
            mma_tf32(acc, qf[k8], bb);
        }
        int c = ni * 8 + gk * 2;
        float2 b0 = *(const float2*)&biasp[(rb + gm)     * NTOK + c];
        float2 b1 = *(const float2*)&biasp[(rb + gm + 8) * NTOK + c];
        float2 m0 = *(const float2*)&maskp[(rb + gm)     * NTOK + c];
        float2 m1 = *(const float2*)&maskp[(rb + gm + 8) * NTOK + c];
        p[ni][0] = acc[0] * SCALE + b0.x + m0.x;
        p[ni][1] = acc[1] * SCALE + b0.y + m0.y;
        p[ni][2] = acc[2] * SCALE + b1.x + m1.x;
        p[ni][3] = acc[3] * SCALE + b1.y + m1.y;
    }

    float mx0 = -1e30f, mx1 = -1e30f;
    #pragma unroll
    for (int ni = 0; ni < 18; ni++) {
        mx0 = fmaxf(mx0, fmaxf(p[ni][0], p[ni][1]));
        mx1 = fmaxf(mx1, fmaxf(p[ni][2], p[ni][3]));
    }
    mx0 = fmaxf(mx0, __shfl_xor_sync(0xffffffffu, mx0, 1));
    mx1 = fmaxf(mx1, __shfl_xor_sync(0xffffffffu, mx1, 1));
    mx0 = fmaxf(mx0, __shfl_xor_sync(0xffffffffu, mx0, 2));
    mx1 = fmaxf(mx1, __shfl_xor_sync(0xffffffffu, mx1, 2));

    float s0 = 0.f, s1 = 0.f;
    #pragma unroll
    for (int ni = 0; ni < 18; ni++) {
        p[ni][0] = __expf(p[ni][0] - mx0);
        p[ni][1] = __expf(p[ni][1] - mx0);
        p[ni][2] = __expf(p[ni][2] - mx1);
        p[ni][3] = __expf(p[ni][3] - mx1);
        s0 += p[ni][0] + p[ni][1];
        s1 += p[ni][2] + p[ni][3];
    }
    s0 += __shfl_xor_sync(0xffffffffu, s0, 1);
    s1 += __shfl_xor_sync(0xffffffffu, s1, 1);
    s0 += __shfl_xor_sync(0xffffffffu, s0, 2);
    s1 += __shfl_xor_sync(0xffffffffu, s1, 2);
    const float inv0 = 1.f / s0, inv1 = 1.f / s1;

    float vacc[4][4];
    #pragma unroll
    for (int nd = 0; nd < 4; nd++)
        #pragma unroll
        for (int l = 0; l < 4; l++) vacc[nd][l] = 0.f;

    const int base  = lane & ~3;
    const int src01 = base + (gk >> 1);
    const int src23 = src01 + 2;
    const bool odd  = (gk & 1);

    #pragma unroll
    for (int ni = 0; ni < 18; ni++) {
        float t0 = __shfl_sync(0xffffffffu, p[ni][0], src01);
        float t1 = __shfl_sync(0xffffffffu, p[ni][1], src01);
        float t2 = __shfl_sync(0xffffffffu, p[ni][2], src01);
        float t3 = __shfl_sync(0xffffffffu, p[ni][3], src01);
        float u0 = __shfl_sync(0xffffffffu, p[ni][0], src23);
        float u1 = __shfl_sync(0xffffffffu, p[ni][1], src23);
        float u2 = __shfl_sync(0xffffffffu, p[ni][2], src23);
        float u3 = __shfl_sync(0xffffffffu, p[ni][3], src23);
        uint32_t af[4];
        af[0] = f2tf((odd ? t1 : t0) * inv0);
        af[1] = f2tf((odd ? t3 : t2) * inv1);
        af[2] = f2tf((odd ? u1 : u0) * inv0);
        af[3] = f2tf((odd ? u3 : u2) * inv1);
        #pragma unroll
        for (int nd = 0; nd < 4; nd++) {
            uint32_t bb[2] = {sv[(ni * 8 + gk    ) * AQ_ST + nd * 8 + gm],
                              sv[(ni * 8 + gk + 4) * AQ_ST + nd * 8 + gm]};
            mma_tf32(vacc[nd], af, bb);
        }
    }

    const size_t obase = (size_t)b * NTOK * DIMC + (size_t)h * HD;
    #pragma unroll
    for (int nd = 0; nd < 4; nd++) {
        int c = nd * 8 + gk * 2;
        *(float2*)&g_ctx[obase + (size_t)(rb + gm)     * DIMC + c] =
            make_float2(__uint_as_float(f2tf(vacc[nd][0])), __uint_as_float(f2tf(vacc[nd][1])));
        *(float2*)&g_ctx[obase + (size_t)(rb + gm + 8) * DIMC + c] =
            make_float2(__uint_as_float(f2tf(vacc[nd][2])), __uint_as_float(f2tf(vacc[nd][3])));
    }
}

// ---------------------------------------------------------------------------
// launch
// ---------------------------------------------------------------------------
extern "C" void kernel_launch(void* const* d_in, const int* in_sizes, int n_in,
                              void* d_out, int out_size)
{
    const float* x      = (const float*)d_in[0];
    const float* mask   = (const float*)d_in[1];
    const float* qkv_w  = (const float*)d_in[2];
    const float* qkv_b  = (const float*)d_in[3];
    const float* proj_w = (const float*)d_in[4];
    const float* proj_b = (const float*)d_in[5];
    const float* table  = (const float*)d_in[6];
    const int*   rel    = (const int*)d_in[7];
    float* out = (float*)d_out;

    float* d_xtf;  cudaGetSymbolAddress((void**)&d_xtf,  g_xtf);
    float* d_wqtf; cudaGetSymbolAddress((void**)&d_wqtf, g_wqtf);
    float* d_wptf; cudaGetSymbolAddress((void**)&d_wptf, g_wptf);

    // 0: bias expand + tf32 pre-rounding of x and weights
    bias_expand_kernel<<<(NH * NTOK2 + 255) / 256, 256>>>(table, rel);
    cvt_tf32_kernel<<<(MTOT * DIMC / 4 + 255) / 256, 256>>>(x, d_xtf, MTOT * DIMC / 4);
    cvt_tf32_kernel<<<(1536 * DIMC / 4 + 255) / 256, 256>>>(qkv_w, d_wqtf, 1536 * DIMC / 4);
    cvt_tf32_kernel<<<(DIMC * DIMC / 4 + 255) / 256, 256>>>(proj_w, d_wptf, DIMC * DIMC / 4);

    cudaFuncSetAttribute(gemm_tc_kernel<0>, cudaFuncAttributeMaxDynamicSharedMemorySize, GEMM_SMEM);
    cudaFuncSetAttribute(gemm_tc_kernel<1>, cudaFuncAttributeMaxDynamicSharedMemorySize, GEMM_SMEM);

    // 1: QKV GEMM (M=110592, N=1536) -> g_qkv (tf32 bits)
    gemm_tc_kernel<0><<<(MTOT / BM) * 12, 256, GEMM_SMEM>>>(qkv_b, nullptr);

    // 2: attention (flash-style, register scores, 2 CTAs/SM)
    cudaFuncSetAttribute(attn_kernel, cudaFuncAttributeMaxDynamicSharedMemorySize, ATTN_SMEM);
    attn_kernel<<<B_TOT * NH, 288, ATTN_SMEM>>>(mask);

    // 3: proj GEMM (M=110592, N=512) -> out (fp32)
    gemm_tc_kernel<1><<<(MTOT / BM) * 4, 256, GEMM_SMEM>>>(proj_b, out);
}

// round 17
// speedup vs baseline: 1.7262x; 1.7262x over previous
#include <cuda_runtime.h>
#include <cuda_fp16.h>
#include <cstdint>

// ---------------------------------------------------------------------------
// WindowAttention3D: B=768, N=144, C=512, H=16, hd=32, NW=96
// Round 17: full fp16 (m16n8k16) pipeline — half the mma instructions, half
//           the operand bytes, shfl-free PV repack. fp32 accum everywhere.
// ---------------------------------------------------------------------------

#define B_TOT   768
#define NTOK    144
#define DIMC    512
#define NH      16
#define HD      32
#define NWIN    96
#define SCALE   0.17677669529663687f   // 1/sqrt(32)
#define NTOK2   (NTOK*NTOK)            // 20736
#define BHSTRIDE (NTOK*HD)             // 4608
#define MTOT    (B_TOT*NTOK)           // 110592

// Scratch (device globals; allocation-free rule)
__device__ __half g_qkv[3u*768u*16u*144u*32u]; // [3][B][H][N][hd] fp16
__device__ __half g_ctx[768u*144u*512u];       // [B][N][C]        fp16
__device__ float  g_bias[16u*144u*144u];       // [H][N][N]        fp32
__device__ __half g_xh[110592u*512u];          // x   fp16
__device__ __half g_wqh[1536u*512u];           // qkv_w fp16
__device__ __half g_wph[512u*512u];            // proj_w fp16

// ---------------------------------------------------------------------------
__device__ __forceinline__ uint32_t pack_h2(float a, float b) {
    __half2 h = __floats2half2_rn(a, b);
    return *reinterpret_cast<uint32_t*>(&h);
}

__device__ __forceinline__ void mma_f16(float* c, const uint32_t* a, const uint32_t* b) {
    asm volatile(
        "mma.sync.aligned.m16n8k16.row.col.f32.f16.f16.f32 "
        "{%0,%1,%2,%3},{%4,%5,%6,%7},{%8,%9},{%0,%1,%2,%3};\n"
        : "+f"(c[0]), "+f"(c[1]), "+f"(c[2]), "+f"(c[3])
        : "r"(a[0]), "r"(a[1]), "r"(a[2]), "r"(a[3]), "r"(b[0]), "r"(b[1]));
}

__device__ __forceinline__ uint32_t smem_u32(const void* p) {
    uint32_t a;
    asm("{ .reg .u64 t; cvta.to.shared.u64 t, %1; cvt.u32.u64 %0, t; }" : "=r"(a) : "l"(p));
    return a;
}

__device__ __forceinline__ void cp16(uint32_t saddr, const void* g) {
    asm volatile("cp.async.cg.shared.global [%0], [%1], 16;" :: "r"(saddr), "l"(g));
}
#define CP_COMMIT() asm volatile("cp.async.commit_group;" ::: "memory")
#define CP_WAIT2()  asm volatile("cp.async.wait_group 2;"  ::: "memory")

// ---------------------------------------------------------------------------
// Kernel: expand relative position bias table -> g_bias[h][n][m]
// ---------------------------------------------------------------------------
__global__ __launch_bounds__(256) void bias_expand_kernel(
    const float* __restrict__ table, const int* __restrict__ rel)
{
    int i = blockIdx.x * 256 + threadIdx.x;
    const int total = NH * NTOK2;
    if (i >= total) return;
    int h  = i / NTOK2;
    int nm = i - h * NTOK2;
    g_bias[i] = table[rel[nm] * NH + h];
}

// ---------------------------------------------------------------------------
// Kernel: fp32 -> fp16 (rn), float4 granular
// ---------------------------------------------------------------------------
__global__ __launch_bounds__(256) void cvt_f2h_kernel(
    const float* __restrict__ in, __half* __restrict__ out, int n4)
{
    int i = blockIdx.x * 256 + threadIdx.x;
    if (i >= n4) return;
    float4 v = ((const float4*)in)[i];
    uint2 r;
    r.x = pack_h2(v.x, v.y);
    r.y = pack_h2(v.z, v.w);
    ((uint2*)out)[i] = r;
}

// ---------------------------------------------------------------------------
// FP16 GEMM: Out[m,n] = sum_k A[m,k]*W[n,k] + bias[n]
// BM=256, BN=128, BK=32 halves, 256 threads (8 warps, 4x2), warp tile 64x64.
// 4-stage cp.async; m16n8k16 mma, fragments as self-indexed half2 LDS.32.
// MODE 0: A=g_xh, W=g_wqh, N=1536, scatter half2 to g_qkv.
// MODE 1: A=g_ctx, W=g_wph, N=512, fp32 out.
// ---------------------------------------------------------------------------
#define BM 256
#define BN 128
#define BKH 32                     // k per tile, in halves
#define RST 20                     // row stride in words (40 halves, padded)
#define AW (BM*RST)                // 5120 words / stage
#define BW (BN*RST)                // 2560 words / stage
#define STAGES 4
#define KTILES (DIMC/BKH)          // 16
#define GEMM_SMEM (STAGES*(AW+BW)*4)   // 122880 B

template <int MODE>
__global__ __launch_bounds__(256) void gemm_h_kernel(
    const float* __restrict__ bias, float* __restrict__ Out)
{
    extern __shared__ uint32_t sh[];
    const uint32_t sbase = smem_u32(sh);

    const int nT = (MODE == 0) ? 12 : 4;
    const int m_tile = blockIdx.x / nT;
    const int n_tile = blockIdx.x - m_tile * nT;
    const int m0 = m_tile * BM, n0 = n_tile * BN;

    const int tid  = threadIdx.x;
    const int warp = tid >> 5, lane = tid & 31;
    const int wm = warp >> 1;     // 0..3 (64 rows)
    const int wn = warp & 1;      // 0..1 (64 cols)
    const int gm = lane >> 2, gk = lane & 3;

    const __half* __restrict__ Aptr = (MODE == 0 ? g_xh : g_ctx) + (size_t)m0 * DIMC;
    const __half* __restrict__ Wptr = (MODE == 0 ? g_wqh : g_wph) + (size_t)n0 * DIMC;

    const int lr = tid >> 2;          // 0..63
    const int lcw = (tid & 3) * 4;    // word chunk {0,4,8,12} (16B each)
    const int lch = (tid & 3) * 8;    // same chunk in halves
    const uint32_t a_sm0 = sbase;
    const uint32_t b_sm0 = sbase + STAGES * AW * 4;

    float acc[4][8][4];
    #pragma unroll
    for (int im = 0; im < 4; im++)
        #pragma unroll
        for (int in = 0; in < 8; in++)
            #pragma unroll
            for (int l = 0; l < 4; l++) acc[im][in][l] = 0.f;

    auto issue = [&](int t) {
        const int st = t & (STAGES - 1);
        const int kf = t * BKH;
        const uint32_t ab = a_sm0 + st * AW * 4;
        #pragma unroll
        for (int j = 0; j < 4; j++) {
            int r = lr + j * 64;
            cp16(ab + (r * RST + lcw) * 4, Aptr + (size_t)r * DIMC + kf + lch);
        }
        const uint32_t bb = b_sm0 + st * BW * 4;
        #pragma unroll
        for (int j = 0; j < 2; j++) {
            int r = lr + j * 64;
            cp16(bb + (r * RST + lcw) * 4, Wptr + (size_t)r * DIMC + kf + lch);
        }
    };

    issue(0); CP_COMMIT();
    issue(1); CP_COMMIT();
    issue(2); CP_COMMIT();

    for (int t = 0; t < KTILES; t++) {
        CP_WAIT2();
        __syncthreads();
        if (t + 3 < KTILES) issue(t + 3);
        CP_COMMIT();

        const int st = t & (STAGES - 1);
        const uint32_t* __restrict__ a_s = sh + st * AW;
        const uint32_t* __restrict__ b_s = sh + STAGES * AW + st * BW;

        // two m16n8k16 k-steps per 32-half tile; half2 word base 0 / 8
        #pragma unroll
        for (int ks = 0; ks < 16; ks += 8) {
            uint32_t afr[4][4], bfr[8][2];
            #pragma unroll
            for (int im = 0; im < 4; im++) {
                int rb = wm * 64 + im * 16;
                afr[im][0] = a_s[(rb + gm    ) * RST + ks + gk    ];
                afr[im][1] = a_s[(rb + gm + 8) * RST + ks + gk    ];
                afr[im][2] = a_s[(rb + gm    ) * RST + ks + gk + 4];
                afr[im][3] = a_s[(rb + gm + 8) * RST + ks + gk + 4];
            }
            #pragma unroll
            for (int in = 0; in < 8; in++) {
                int cb = wn * 64 + in * 8;
                bfr[in][0] = b_s[(cb + gm) * RST + ks + gk    ];
                bfr[in][1] = b_s[(cb + gm) * RST + ks + gk + 4];
            }
            #pragma unroll
            for (int im = 0; im < 4; im++)
                #pragma unroll
                for (int in = 0; in < 8; in++)
                    mma_f16(acc[im][in], afr[im], bfr[in]);
        }
    }

    // epilogue: bias add + store/scatter
    #pragma unroll
    for (int im = 0; im < 4; im++) {
        #pragma unroll
        for (int half = 0; half < 2; half++) {
            int rg = m0 + wm * 64 + im * 16 + gm + half * 8;
            int b_idx = rg / NTOK;
            int ntk   = rg - b_idx * NTOK;
            #pragma unroll
            for (int in = 0; in < 8; in++) {
                int cg = n0 + wn * 64 + in * 8 + gk * 2;
                float v0 = acc[im][in][half * 2 + 0] + bias[cg];
                float v1 = acc[im][in][half * 2 + 1] + bias[cg + 1];
                if (MODE == 0) {
                    int which = cg >> 9;
                    int rem   = cg & 511;
                    int h     = rem >> 5;
                    int d     = rem & 31;
                    size_t dst = ((size_t)(which * B_TOT + b_idx) * NH + h) * BHSTRIDE
                               + (size_t)ntk * HD + d;
                    *(uint32_t*)&g_qkv[dst] = pack_h2(v0, v1);
                } else {
                    *(float2*)&Out[(size_t)rg * DIMC + cg] = make_float2(v0, v1);
                }
            }
        }
    }
}

// ---------------------------------------------------------------------------
// Attention per (b,h): 288 threads (9 warps), 16 rows/warp, scores in regs,
// quad-shfl softmax, SHFL-FREE fp16 PV repack (C-frag pairs == A-frag),
// v staged transposed [d][tok] for B-frags. 2 CTAs/SM.
// ---------------------------------------------------------------------------
#define QST 20                     // q/k row stride, words (40 halves)
#define VST 76                     // vT row stride, words (152 halves)
// smem: sq 144*20 + sk 144*20 + svT 32*76 = 8192 words = 32 KB

__global__ __launch_bounds__(288, 2) void attn_kernel(const float* __restrict__ mask)
{
    __shared__ uint32_t sq[NTOK * QST];
    __shared__ uint32_t sk[NTOK * QST];
    __shared__ uint32_t svT[32 * VST];

    const int bh = blockIdx.x;
    const int b  = bh >> 4, h = bh & 15;
    const int w  = b % NWIN;

    const int tid  = threadIdx.x;
    const int lane = tid & 31;
    const int warp = tid >> 5;
    const int gm = lane >> 2, gk = lane & 3;
    const int rb = warp * 16;

    const __half* qg = g_qkv + ((size_t)(0 * B_TOT + b) * NH + h) * BHSTRIDE;
    const __half* kg = g_qkv + ((size_t)(1 * B_TOT + b) * NH + h) * BHSTRIDE;
    const __half* vg = g_qkv + ((size_t)(2 * B_TOT + b) * NH + h) * BHSTRIDE;

    // stage q,k rows (16 words of 2 halves per row) + v transposed
    {
        const uint32_t* qw = (const uint32_t*)qg;
        const uint32_t* kw = (const uint32_t*)kg;
        const uint32_t* vw = (const uint32_t*)vg;
        __half* svh = (__half*)svT;
        for (int i = tid; i < NTOK * 16; i += 288) {
            int row = i >> 4, wd = i & 15;
            sq[row * QST + wd] = qw[row * 16 + wd];
            sk[row * QST + wd] = kw[row * 16 + wd];
            uint32_t hv = vw[row * 16 + wd];
            __half2 hh = *reinterpret_cast<__half2*>(&hv);
            svh[(2 * wd    ) * (2 * VST) + row] = hh.x;   // d=2wd,   tok=row
            svh[(2 * wd + 1) * (2 * VST) + row] = hh.y;   // d=2wd+1
        }
    }
    __syncthreads();

    const float* __restrict__ biasp = g_bias + (size_t)h * NTOK2;
    const float* __restrict__ maskp = mask   + (size_t)w * NTOK2;

    // Q fragments: 2 k16 steps cover hd=32
    uint32_t qf[2][4];
    #pragma unroll
    for (int kt = 0; kt < 2; kt++) {
        qf[kt][0] = sq[(rb + gm    ) * QST + kt * 8 + gk    ];
        qf[kt][1] = sq[(rb + gm + 8) * QST + kt * 8 + gk    ];
        qf[kt][2] = sq[(rb + gm    ) * QST + kt * 8 + gk + 4];
        qf[kt][3] = sq[(rb + gm + 8) * QST + kt * 8 + gk + 4];
    }

    // ---- S = scale*q@k^T + bias + mask in registers p[18][4] ----
    float p[18][4];
    #pragma unroll
    for (int ni = 0; ni < 18; ni++) {
        float acc[4] = {0.f, 0.f, 0.f, 0.f};
        #pragma unroll
        for (int kt = 0; kt < 2; kt++) {
            uint32_t bb[2] = {sk[(ni * 8 + gm) * QST + kt * 8 + gk],
                              sk[(ni * 8 + gm) * QST + kt * 8 + gk + 4]};
            mma_f16(acc, qf[kt], bb);
        }
        int c = ni * 8 + gk * 2;
        float2 b0 = *(const float2*)&biasp[(rb + gm)     * NTOK + c];
        float2 b1 = *(const float2*)&biasp[(rb + gm + 8) * NTOK + c];
        float2 m0 = *(const float2*)&maskp[(rb + gm)     * NTOK + c];
        float2 m1 = *(const float2*)&maskp[(rb + gm + 8) * NTOK + c];
        p[ni][0] = acc[0] * SCALE + b0.x + m0.x;
        p[ni][1] = acc[1] * SCALE + b0.y + m0.y;
        p[ni][2] = acc[2] * SCALE + b1.x + m1.x;
        p[ni][3] = acc[3] * SCALE + b1.y + m1.y;
    }

    // ---- softmax in registers (rows gm and gm+8) ----
    float mx0 = -1e30f, mx1 = -1e30f;
    #pragma unroll
    for (int ni = 0; ni < 18; ni++) {
        mx0 = fmaxf(mx0, fmaxf(p[ni][0], p[ni][1]));
        mx1 = fmaxf(mx1, fmaxf(p[ni][2], p[ni][3]));
    }
    mx0 = fmaxf(mx0, __shfl_xor_sync(0xffffffffu, mx0, 1));
    mx1 = fmaxf(mx1, __shfl_xor_sync(0xffffffffu, mx1, 1));
    mx0 = fmaxf(mx0, __shfl_xor_sync(0xffffffffu, mx0, 2));
    mx1 = fmaxf(mx1, __shfl_xor_sync(0xffffffffu, mx1, 2));

    float s0 = 0.f, s1 = 0.f;
    #pragma unroll
    for (int ni = 0; ni < 18; ni++) {
        p[ni][0] = __expf(p[ni][0] - mx0);
        p[ni][1] = __expf(p[ni][1] - mx0);
        p[ni][2] = __expf(p[ni][2] - mx1);
        p[ni][3] = __expf(p[ni][3] - mx1);
        s0 += p[ni][0] + p[ni][1];
        s1 += p[ni][2] + p[ni][3];
    }
    s0 += __shfl_xor_sync(0xffffffffu, s0, 1);
    s1 += __shfl_xor_sync(0xffffffffu, s1, 1);
    s0 += __shfl_xor_sync(0xffffffffu, s0, 2);
    s1 += __shfl_xor_sync(0xffffffffu, s1, 2);
    const float inv0 = 1.f / s0, inv1 = 1.f / s1;

    // ---- O = P @ v: A-frag = local C-frag pairs (no shuffles!) ----
    float vacc[4][4];
    #pragma unroll
    for (int nd = 0; nd < 4; nd++)
        #pragma unroll
        for (int l = 0; l < 4; l++) vacc[nd][l] = 0.f;

    #pragma unroll
    for (int kt = 0; kt < 9; kt++) {          // K = 144 = 9 x 16
        uint32_t af[4];
        af[0] = pack_h2(p[2*kt    ][0] * inv0, p[2*kt    ][1] * inv0); // row gm,  k=16kt+2gk
        af[1] = pack_h2(p[2*kt    ][2] * inv1, p[2*kt    ][3] * inv1); // row gm+8
        af[2] = pack_h2(p[2*kt + 1][0] * inv0, p[2*kt + 1][1] * inv0); // row gm,  k+8
        af[3] = pack_h2(p[2*kt + 1][2] * inv1, p[2*kt + 1][3] * inv1); // row gm+8
        #pragma unroll
        for (int nd = 0; nd < 4; nd++) {
            int d = nd * 8 + gm;
            uint32_t bb[2] = {svT[d * VST + kt * 8 + gk],
                              svT[d * VST + kt * 8 + gk + 4]};
            mma_f16(vacc[nd], af, bb);
        }
    }

    // store O -> g_ctx[b, n, h*32 + d] as fp16
    const size_t obase = (size_t)b * NTOK * DIMC + (size_t)h * HD;
    #pragma unroll
    for (int nd = 0; nd < 4; nd++) {
        int c = nd * 8 + gk * 2;
        *(uint32_t*)&g_ctx[obase + (size_t)(rb + gm)     * DIMC + c] =
            pack_h2(vacc[nd][0], vacc[nd][1]);
        *(uint32_t*)&g_ctx[obase + (size_t)(rb + gm + 8) * DIMC + c] =
            pack_h2(vacc[nd][2], vacc[nd][3]);
    }
}

// ---------------------------------------------------------------------------
// launch (ordered so the profiled slot #4 is the QKV GEMM)
// ---------------------------------------------------------------------------
extern "C" void kernel_launch(void* const* d_in, const int* in_sizes, int n_in,
                              void* d_out, int out_size)
{
    const float* x      = (const float*)d_in[0];
    const float* mask   = (const float*)d_in[1];
    const float* qkv_w  = (const float*)d_in[2];
    const float* qkv_b  = (const float*)d_in[3];
    const float* proj_w = (const float*)d_in[4];
    const float* proj_b = (const float*)d_in[5];
    const float* table  = (const float*)d_in[6];
    const int*   rel    = (const int*)d_in[7];
    float* out = (float*)d_out;

    __half* d_xh;  cudaGetSymbolAddress((void**)&d_xh,  g_xh);
    __half* d_wqh; cudaGetSymbolAddress((void**)&d_wqh, g_wqh);
    __half* d_wph; cudaGetSymbolAddress((void**)&d_wph, g_wph);

    cudaFuncSetAttribute(gemm_h_kernel<0>, cudaFuncAttributeMaxDynamicSharedMemorySize, GEMM_SMEM);
    cudaFuncSetAttribute(gemm_h_kernel<1>, cudaFuncAttributeMaxDynamicSharedMemorySize, GEMM_SMEM);

    // 1: cvt x  2: cvt qkv_w  3: bias expand
    cvt_f2h_kernel<<<(MTOT * DIMC / 4 + 255) / 256, 256>>>(x, d_xh, MTOT * DIMC / 4);
    cvt_f2h_kernel<<<(1536 * DIMC / 4 + 255) / 256, 256>>>(qkv_w, d_wqh, 1536 * DIMC / 4);
    bias_expand_kernel<<<(NH * NTOK2 + 255) / 256, 256>>>(table, rel);

    // 4: QKV GEMM (M=110592, N=1536) -> g_qkv (fp16)   [profiled slot]
    gemm_h_kernel<0><<<(MTOT / BM) * 12, 256, GEMM_SMEM>>>(qkv_b, nullptr);

    // 5: cvt proj_w
    cvt_f2h_kernel<<<(DIMC * DIMC / 4 + 255) / 256, 256>>>(proj_w, d_wph, DIMC * DIMC / 4);

    // 6: attention
    attn_kernel<<<B_TOT * NH, 288>>>(mask);

    // 7: proj GEMM (M=110592, N=512) -> out (fp32)
    gemm_h_kernel<1><<<(MTOT / BM) * 4, 256, GEMM_SMEM>>>(proj_b, out);
}